// round 13
// baseline (speedup 1.0000x reference)
#include <cuda_runtime.h>
#include <cuda_fp16.h>
#include <cstdint>
#include <math.h>

#define T_STEPS 512
#define BATCH   64
#define DENC    1536
#define HID     30
#define NG      120
#define NCOL    128
#define MROWS   (BATCH * T_STEPS)
#define KCH     64
#define NCHUNK  (DENC / KCH)      // 24

// ---------------- device scratch ----------------
// g_pre packed layout: col 4k+g = gate g (i,f,g,o) of unit k; col 120=xa, 121=xb
__device__ float   g_pre[(size_t)MROWS * NCOL];
__device__ __half  g_Bhi[NCOL * DENC];
__device__ __half  g_Blo[NCOL * DENC];

// ---------------- helpers ----------------
__device__ __forceinline__ uint32_t smem_u32(const void* p) {
    uint32_t a;
    asm("{ .reg .u64 t; cvta.to.shared.u64 t, %1; cvt.u32.u64 %0, t; }" : "=r"(a) : "l"(p));
    return a;
}
__device__ __forceinline__ uint32_t swz(uint32_t off) { return off ^ ((off >> 3) & 0x70); }

__device__ __forceinline__ void cp16(uint32_t dst, const void* src) {
    asm volatile("cp.async.cg.shared.global [%0], [%1], 16;" :: "r"(dst), "l"(src));
}
__device__ __forceinline__ void cp_commit() { asm volatile("cp.async.commit_group;"); }
template <int N> __device__ __forceinline__ void cp_wait() {
    asm volatile("cp.async.wait_group %0;" :: "n"(N));
}

__device__ __forceinline__ void ldsm4(uint32_t& r0, uint32_t& r1, uint32_t& r2, uint32_t& r3,
                                      uint32_t addr) {
    asm volatile("ldmatrix.sync.aligned.m8n8.x4.shared.b16 {%0,%1,%2,%3}, [%4];"
                 : "=r"(r0), "=r"(r1), "=r"(r2), "=r"(r3) : "r"(addr));
}
__device__ __forceinline__ void mma16816(float* c, const uint32_t* a, const uint32_t* b) {
    asm volatile(
        "mma.sync.aligned.m16n8k16.row.col.f32.f16.f16.f32 "
        "{%0,%1,%2,%3}, {%4,%5,%6,%7}, {%8,%9}, {%0,%1,%2,%3};"
        : "+f"(c[0]), "+f"(c[1]), "+f"(c[2]), "+f"(c[3])
        : "r"(a[0]), "r"(a[1]), "r"(a[2]), "r"(a[3]), "r"(b[0]), "r"(b[1]));
}
__device__ __forceinline__ uint32_t cvt_h2(float hi, float lo) {
    uint32_t r;
    asm("cvt.rn.f16x2.f32 %0, %1, %2;" : "=r"(r) : "f"(hi), "f"(lo));
    return r;
}

// ---------------- Phase 0: pack W -> fp16 hi/lo, PERMUTED rows ----------------
// packed row p<120 -> orig gate row (p&3)*30 + (p>>2); p==120 -> Wa; p==121 -> Wb
__global__ void pack_kernel(const float* __restrict__ Wih, const float* __restrict__ Wa,
                            const float* __restrict__ Wb) {
    int idx = blockIdx.x * blockDim.x + threadIdx.x;
    if (idx >= NCOL * DENC) return;
    int n = idx / DENC, k = idx % DENC;
    float v = 0.f;
    if (n < NG) {
        int r = (n & 3) * 30 + (n >> 2);
        v = Wih[r * (DENC + 1) + k];
    } else if (n == NG)     v = Wa[k];
    else if (n == NG + 1)   v = Wb[k];
    __half hi = __float2half_rn(v);
    float r = v - __half2float(hi);
    g_Bhi[idx] = hi;
    g_Blo[idx] = __float2half_rn(r);
}

// ---------------- Phase 1: HMMA GEMM (unchanged) ----------------
#define SMEM_DYN (1024 + 128 * 1024)

__global__ __launch_bounds__(256) void gemm_kernel(const float* __restrict__ X,
                                                   int blk_off) {
    extern __shared__ char dsm[];
    const uint32_t raw = smem_u32(dsm);
    const uint32_t base = (raw + 1023) & ~1023u;
    char* smb = dsm + (base - raw);
    const uint32_t AH = base;
    const uint32_t BQ = base + 32768;

    const int tid = threadIdx.x, lane = tid & 31, wid = tid >> 5;
    const int warp_m = wid & 3, warp_n = wid >> 2;
    const int m0 = (blockIdx.x + blk_off) * 128;

    float acc[2][8][4];
#pragma unroll
    for (int mi = 0; mi < 2; mi++)
#pragma unroll
        for (int ni = 0; ni < 8; ni++)
#pragma unroll
            for (int q = 0; q < 4; q++) acc[mi][ni][q] = 0.f;

    auto issueB = [&](int s, int k0) {
        uint32_t bs = BQ + s * 32768;
#pragma unroll
        for (int j = 0; j < 4; j++) {
            int u = tid + j * 256;
            int row = u >> 3, c = u & 7;
            uint32_t d = swz((uint32_t)(row * 128 + c * 16));
            size_t go = (size_t)row * DENC + k0 + c * 8;
            cp16(bs + d, g_Bhi + go);
            cp16(bs + 16384 + d, g_Blo + go);
        }
        cp_commit();
    };

    const int xrow = tid >> 1, xcb = (tid & 1) * 32;
    const float* Xrow = X + (size_t)(m0 + xrow) * DENC + xcb;
    uint32_t soff[4];
#pragma unroll
    for (int j = 0; j < 4; j++)
        soff[j] = swz((uint32_t)(xrow * 128 + (tid & 1) * 64 + 16 * j));

    auto stsA = [&](int st, int k0) {
        float4 xr[8];
#pragma unroll
        for (int j = 0; j < 8; j++) xr[j] = *(const float4*)(Xrow + k0 + 4 * j);
#pragma unroll
        for (int j = 0; j < 4; j++) {
            uint4 h;
            h.x = cvt_h2(xr[2 * j].y,     xr[2 * j].x);
            h.y = cvt_h2(xr[2 * j].w,     xr[2 * j].z);
            h.z = cvt_h2(xr[2 * j + 1].y, xr[2 * j + 1].x);
            h.w = cvt_h2(xr[2 * j + 1].w, xr[2 * j + 1].z);
            *(uint4*)(smb + (AH - base) + st * 16384 + soff[j]) = h;
        }
    };

    const int a_row = warp_m * 32 + ((lane >> 3) & 1) * 8 + (lane & 7);
    const int a_kb  = (lane >> 4) * 16;
    const int b_row = warp_n * 64 + ((lane >> 4) & 1) * 8 + (lane & 7);
    const int b_kb  = ((lane >> 3) & 1) * 16;

    issueB(0, 0);
    issueB(1, KCH);
    stsA(0, 0);

    for (int i = 0; i < NCHUNK; i++) {
        if (i + 1 < NCHUNK) cp_wait<1>(); else cp_wait<0>();
        __syncthreads();

        const uint32_t as = AH + (i & 1) * 16384;
        const uint32_t bs = BQ + (i % 3) * 32768;
#pragma unroll
        for (int k = 0; k < 4; k++) {
            const int kbyte = k * 32;
            uint32_t a[2][4];
#pragma unroll
            for (int mi = 0; mi < 2; mi++) {
                uint32_t ao = swz((uint32_t)((a_row + mi * 16) * 128 + a_kb + kbyte));
                ldsm4(a[mi][0], a[mi][1], a[mi][2], a[mi][3], as + ao);
            }
            uint32_t bh[8][2], bl[8][2];
#pragma unroll
            for (int n2 = 0; n2 < 4; n2++) {
                uint32_t bo = swz((uint32_t)((b_row + n2 * 16) * 128 + b_kb + kbyte));
                ldsm4(bh[2 * n2][0], bh[2 * n2][1], bh[2 * n2 + 1][0], bh[2 * n2 + 1][1],
                      bs + bo);
                ldsm4(bl[2 * n2][0], bl[2 * n2][1], bl[2 * n2 + 1][0], bl[2 * n2 + 1][1],
                      bs + 16384 + bo);
            }
#pragma unroll
            for (int mi = 0; mi < 2; mi++)
#pragma unroll
                for (int ni = 0; ni < 8; ni++) {
                    mma16816(acc[mi][ni], a[mi], bh[ni]);
                    mma16816(acc[mi][ni], a[mi], bl[ni]);
                }
        }

        if (i + 1 < NCHUNK) stsA((i + 1) & 1, (i + 1) * KCH);
        if (i + 2 < NCHUNK) issueB((i + 2) % 3, (i + 2) * KCH);
    }

    const int erow = m0 + warp_m * 32 + (lane >> 2);
    const int ecol = warp_n * 64 + (lane & 3) * 2;
#pragma unroll
    for (int mi = 0; mi < 2; mi++)
#pragma unroll
        for (int ni = 0; ni < 8; ni++) {
            float* p = g_pre + (size_t)(erow + mi * 16) * NCOL + ecol + ni * 8;
            *(float2*)p              = make_float2(acc[mi][ni][0], acc[mi][ni][1]);
            *(float2*)(p + 8 * NCOL) = make_float2(acc[mi][ni][2], acc[mi][ni][3]);
        }
}

// ---------------- Phase 2: single-warp recurrence (scalar body + deep prefetch) ----------------
__device__ __forceinline__ float ex2a(float x) { float y; asm("ex2.approx.f32 %0,%1;" : "=f"(y) : "f"(x)); return y; }
__device__ __forceinline__ float lg2a(float x) { float y; asm("lg2.approx.f32 %0,%1;" : "=f"(y) : "f"(x)); return y; }
__device__ __forceinline__ float tanha(float x) { float y; asm("tanh.approx.f32 %0,%1;" : "=f"(y) : "f"(x)); return y; }
__device__ __forceinline__ float rcpa(float x) { float y; asm("rcp.approx.f32 %0,%1;" : "=f"(y) : "f"(x)); return y; }
__device__ __forceinline__ float sigm_f(float x) { return fmaf(tanha(0.5f * x), 0.5f, 0.5f); }
__device__ __forceinline__ float sp_clip(float x) {
    const float LOG2E = 1.4426950408889634f, LN2 = 0.6931471805599453f;
    float e = ex2a(-fabsf(x) * LOG2E);
    float sp = fmaxf(x, 0.f) + lg2a(1.f + e) * LN2;
    return fminf(fmaxf(sp, 1e-6f), 100.f);
}

// One warp per batch. Scalar FFMA body (no u64 pair-MOV bloat): 4 gate chains,
// 2-way split; lanes 30/31 carry Wa/Wb in their i-chain -> a/b logits free.
// Memory: 4-deep LDG.128 prefetch pipeline + precomputed lg2(1-u) in smem.
__global__ __launch_bounds__(32) void seq_kernel(const float* __restrict__ u,
                                                 const float* __restrict__ Wih,
                                                 const float* __restrict__ Whh,
                                                 const float* __restrict__ bih,
                                                 const float* __restrict__ bhh,
                                                 const float* __restrict__ Wa,
                                                 const float* __restrict__ ba,
                                                 const float* __restrict__ Wb,
                                                 const float* __restrict__ bb,
                                                 float* __restrict__ out,
                                                 int b_off) {
    __shared__ float lgu_s[T_STEPS];
    const int b = blockIdx.x + b_off;
    const int lane = threadIdx.x;
    const bool ul = lane < HID;

    float wi[HID], wf[HID], wg[HID], wo[HID];
    float bi, bf = 0.f, bg = 0.f, bo = 0.f;
    float wzi = 0.f, wzf = 0.f, wzg = 0.f, wzo = 0.f;

    if (ul) {
        const int ri = lane, rf = 30 + lane, rg = 60 + lane, ro = 90 + lane;
        bi = bih[ri] + bhh[ri];
        bf = bih[rf] + bhh[rf];
        bg = bih[rg] + bhh[rg];
        bo = bih[ro] + bhh[ro];
        wzi = Wih[ri * (DENC + 1) + DENC];
        wzf = Wih[rf * (DENC + 1) + DENC];
        wzg = Wih[rg * (DENC + 1) + DENC];
        wzo = Wih[ro * (DENC + 1) + DENC];
#pragma unroll
        for (int j = 0; j < HID; j++) {
            wi[j] = Whh[ri * HID + j];
            wf[j] = Whh[rf * HID + j];
            wg[j] = Whh[rg * HID + j];
            wo[j] = Whh[ro * HID + j];
        }
    } else {
        const float* wr = (lane == HID) ? (Wa + DENC) : (Wb + DENC);
        bi = (lane == HID) ? ba[0] : bb[0];
#pragma unroll
        for (int j = 0; j < HID; j++) {
            wi[j] = wr[j];
            wf[j] = 0.f; wg[j] = 0.f; wo[j] = 0.f;
        }
    }

    const float* urow = u + b * T_STEPS;
    // precompute lg2(1-u) for all steps (one-time, off the recurrence path)
    for (int i = lane; i < T_STEPS; i += 32) {
        float uu = fminf(fmaxf(urow[i], 1e-5f), 1.f - 1e-5f);
        lgu_s[i] = lg2a(1.f - uu);
    }
    __syncwarp();

    float hx = 0.f, c = 0.f;
    const float* prow = g_pre + (size_t)b * T_STEPS * NCOL;
    const int col4 = ul ? (4 * lane) : NG;    // lanes 30/31 read (xa,xb,·,·)

    // 4-deep prefetch pipeline (4 outstanding LDG.128 per lane)
    float4 pbuf[4];
#pragma unroll
    for (int q = 0; q < 4; q++)
        pbuf[q] = *(const float4*)(prow + (size_t)q * NCOL + col4);

#pragma unroll 4
    for (int t = 0; t < T_STEPS; t++) {
        float4 p4 = pbuf[t & 3];
        if (t + 4 < T_STEPS)
            pbuf[t & 3] = *(const float4*)(prow + (size_t)(t + 4) * NCOL + col4);
        float lgu = lgu_s[t];

        // i-chain x-part: lane31 must use p4.y (xb), others p4.x
        float xsel = (lane == 31) ? p4.y : p4.x;

        // 4 scalar gate chains, 2-way latency split each
        float i0 = xsel + bi, i1 = 0.f;
        float f0 = p4.y + bf, f1 = 0.f;
        float g0 = p4.z + bg, g1 = 0.f;
        float o0 = p4.w + bo, o1 = 0.f;
#pragma unroll
        for (int j = 0; j < HID; j += 2) {
            float h0 = __shfl_sync(0xffffffffu, hx, j);
            float h1 = __shfl_sync(0xffffffffu, hx, j + 1);
            i0 = fmaf(h0, wi[j], i0);  i1 = fmaf(h1, wi[j + 1], i1);
            f0 = fmaf(h0, wf[j], f0);  f1 = fmaf(h1, wf[j + 1], f1);
            g0 = fmaf(h0, wg[j], g0);  g1 = fmaf(h1, wg[j + 1], g1);
            o0 = fmaf(h0, wo[j], o0);  o1 = fmaf(h1, wo[j + 1], o1);
        }
        float ai = i0 + i1;            // lane30: a-logit, lane31: b-logit
        float af = f0 + f1;
        float ag = g0 + g1;
        float ao = o0 + o1;

        // HardKuma z (a/b logits live in lanes 30/31's ai)
        float inv_ab = rcpa(sp_clip(ai));
        float inva = __shfl_sync(0xffffffffu, inv_ab, 30);
        float invb = __shfl_sync(0xffffffffu, inv_ab, 31);
        float p = ex2a(lgu * invb);
        float s = ex2a(lg2a(1.f - p) * inva);
        float zt = fminf(fmaxf(fmaf(s, 1.2f, -0.1f), 0.f), 1.f);
        if (lane == 0) out[b * T_STEPS + t] = zt;

        // LSTM update (in-register)
        float gi = fmaf(zt, wzi, ai);
        float gf = fmaf(zt, wzf, af);
        float gg = fmaf(zt, wzg, ag);
        float go_ = fmaf(zt, wzo, ao);
        c = sigm_f(gf) * c + sigm_f(gi) * tanha(gg);
        hx = sigm_f(go_) * tanha(c);
    }
}

// ---------------- launch: forked-stream pipeline ----------------
extern "C" void kernel_launch(void* const* d_in, const int* in_sizes, int n_in,
                              void* d_out, int out_size) {
    const float* x   = (const float*)d_in[0];
    const float* u   = (const float*)d_in[1];
    const float* Wih = (const float*)d_in[2];
    const float* Whh = (const float*)d_in[3];
    const float* bih = (const float*)d_in[4];
    const float* bhh = (const float*)d_in[5];
    const float* Wa  = (const float*)d_in[6];
    const float* ba  = (const float*)d_in[7];
    const float* Wb  = (const float*)d_in[8];
    const float* bb  = (const float*)d_in[9];
    float* out = (float*)d_out;

    static bool inited = false;
    static cudaStream_t s1, s2;
    static cudaEvent_t e1, e2, f1, f2;
    if (!inited) {
        cudaStreamCreateWithFlags(&s1, cudaStreamNonBlocking);
        cudaStreamCreateWithFlags(&s2, cudaStreamNonBlocking);
        cudaEventCreateWithFlags(&e1, cudaEventDisableTiming);
        cudaEventCreateWithFlags(&e2, cudaEventDisableTiming);
        cudaEventCreateWithFlags(&f1, cudaEventDisableTiming);
        cudaEventCreateWithFlags(&f2, cudaEventDisableTiming);
        cudaFuncSetAttribute(gemm_kernel, cudaFuncAttributeMaxDynamicSharedMemorySize,
                             SMEM_DYN);
        inited = true;
    }

    // stream 0: pack -> gemm chunk 1 -> gemm chunk 2
    pack_kernel<<<(NCOL * DENC + 255) / 256, 256>>>(Wih, Wa, Wb);
    gemm_kernel<<<128, 256, SMEM_DYN>>>(x, 0);
    cudaEventRecord(e1, 0);
    gemm_kernel<<<128, 256, SMEM_DYN>>>(x, 128);
    cudaEventRecord(e2, 0);

    // side stream 1: seq for batches 0..31 (overlaps gemm chunk 2)
    cudaStreamWaitEvent(s1, e1, 0);
    seq_kernel<<<32, 32, 0, s1>>>(u, Wih, Whh, bih, bhh, Wa, ba, Wb, bb, out, 0);
    cudaEventRecord(f1, s1);

    // side stream 2: seq for batches 32..63
    cudaStreamWaitEvent(s2, e2, 0);
    seq_kernel<<<32, 32, 0, s2>>>(u, Wih, Whh, bih, bhh, Wa, ba, Wb, bb, out, 32);
    cudaEventRecord(f2, s2);

    // join back into the captured origin stream
    cudaStreamWaitEvent(0, f1, 0);
    cudaStreamWaitEvent(0, f2, 0);
}

// round 14
// speedup vs baseline: 1.3173x; 1.3173x over previous
#include <cuda_runtime.h>
#include <cuda_fp16.h>
#include <cstdint>
#include <math.h>

#define T_STEPS 512
#define BATCH   64
#define DENC    1536
#define HID     30
#define NG      120
#define NCOL    128
#define MROWS   (BATCH * T_STEPS)
#define KCH     64
#define NCHUNK  (DENC / KCH)      // 24

// ---------------- device scratch ----------------
// g_pre packed layout: col 4k+g = gate g (i,f,g,o) of unit k; col 120=xa, 121=xb
__device__ float   g_pre[(size_t)MROWS * NCOL];
__device__ __half  g_Bhi[NCOL * DENC];
__device__ __half  g_Blo[NCOL * DENC];

// ---------------- helpers ----------------
__device__ __forceinline__ uint32_t smem_u32(const void* p) {
    uint32_t a;
    asm("{ .reg .u64 t; cvta.to.shared.u64 t, %1; cvt.u32.u64 %0, t; }" : "=r"(a) : "l"(p));
    return a;
}
__device__ __forceinline__ uint32_t swz(uint32_t off) { return off ^ ((off >> 3) & 0x70); }

__device__ __forceinline__ void cp16(uint32_t dst, const void* src) {
    asm volatile("cp.async.cg.shared.global [%0], [%1], 16;" :: "r"(dst), "l"(src));
}
__device__ __forceinline__ void cp_commit() { asm volatile("cp.async.commit_group;"); }
template <int N> __device__ __forceinline__ void cp_wait() {
    asm volatile("cp.async.wait_group %0;" :: "n"(N));
}

__device__ __forceinline__ void ldsm4(uint32_t& r0, uint32_t& r1, uint32_t& r2, uint32_t& r3,
                                      uint32_t addr) {
    asm volatile("ldmatrix.sync.aligned.m8n8.x4.shared.b16 {%0,%1,%2,%3}, [%4];"
                 : "=r"(r0), "=r"(r1), "=r"(r2), "=r"(r3) : "r"(addr));
}
__device__ __forceinline__ void mma16816(float* c, const uint32_t* a, const uint32_t* b) {
    asm volatile(
        "mma.sync.aligned.m16n8k16.row.col.f32.f16.f16.f32 "
        "{%0,%1,%2,%3}, {%4,%5,%6,%7}, {%8,%9}, {%0,%1,%2,%3};"
        : "+f"(c[0]), "+f"(c[1]), "+f"(c[2]), "+f"(c[3])
        : "r"(a[0]), "r"(a[1]), "r"(a[2]), "r"(a[3]), "r"(b[0]), "r"(b[1]));
}
__device__ __forceinline__ uint32_t cvt_h2(float hi, float lo) {
    uint32_t r;
    asm("cvt.rn.f16x2.f32 %0, %1, %2;" : "=r"(r) : "f"(hi), "f"(lo));
    return r;
}

// f32x2 packed helpers
__device__ __forceinline__ unsigned long long pk2(float lo, float hi) {
    unsigned long long r;
    asm("mov.b64 %0, {%1,%2};" : "=l"(r) : "f"(lo), "f"(hi));
    return r;
}
__device__ __forceinline__ void upk2(unsigned long long v, float& lo, float& hi) {
    asm("mov.b64 {%0,%1}, %2;" : "=f"(lo), "=f"(hi) : "l"(v));
}
__device__ __forceinline__ unsigned long long ffma2(unsigned long long a,
                                                    unsigned long long b,
                                                    unsigned long long c) {
    unsigned long long d;
    asm("fma.rn.f32x2 %0, %1, %2, %3;" : "=l"(d) : "l"(a), "l"(b), "l"(c));
    return d;
}
__device__ __forceinline__ unsigned long long add2(unsigned long long a,
                                                   unsigned long long b) {
    unsigned long long d;
    asm("add.rn.f32x2 %0, %1, %2;" : "=l"(d) : "l"(a), "l"(b));
    return d;
}

// ---------------- Phase 0: pack W -> fp16 hi/lo, PERMUTED rows ----------------
// packed row p<120 -> orig gate row (p&3)*30 + (p>>2); p==120 -> Wa; p==121 -> Wb
__global__ void pack_kernel(const float* __restrict__ Wih, const float* __restrict__ Wa,
                            const float* __restrict__ Wb) {
    int idx = blockIdx.x * blockDim.x + threadIdx.x;
    if (idx >= NCOL * DENC) return;
    int n = idx / DENC, k = idx % DENC;
    float v = 0.f;
    if (n < NG) {
        int r = (n & 3) * 30 + (n >> 2);
        v = Wih[r * (DENC + 1) + k];
    } else if (n == NG)     v = Wa[k];
    else if (n == NG + 1)   v = Wb[k];
    __half hi = __float2half_rn(v);
    float r = v - __half2float(hi);
    g_Bhi[idx] = hi;
    g_Blo[idx] = __float2half_rn(r);
}

// ---------------- Phase 1: HMMA GEMM (unchanged) ----------------
#define SMEM_DYN (1024 + 128 * 1024)

__global__ __launch_bounds__(256) void gemm_kernel(const float* __restrict__ X,
                                                   int blk_off) {
    extern __shared__ char dsm[];
    const uint32_t raw = smem_u32(dsm);
    const uint32_t base = (raw + 1023) & ~1023u;
    char* smb = dsm + (base - raw);
    const uint32_t AH = base;
    const uint32_t BQ = base + 32768;

    const int tid = threadIdx.x, lane = tid & 31, wid = tid >> 5;
    const int warp_m = wid & 3, warp_n = wid >> 2;
    const int m0 = (blockIdx.x + blk_off) * 128;

    float acc[2][8][4];
#pragma unroll
    for (int mi = 0; mi < 2; mi++)
#pragma unroll
        for (int ni = 0; ni < 8; ni++)
#pragma unroll
            for (int q = 0; q < 4; q++) acc[mi][ni][q] = 0.f;

    auto issueB = [&](int s, int k0) {
        uint32_t bs = BQ + s * 32768;
#pragma unroll
        for (int j = 0; j < 4; j++) {
            int u = tid + j * 256;
            int row = u >> 3, c = u & 7;
            uint32_t d = swz((uint32_t)(row * 128 + c * 16));
            size_t go = (size_t)row * DENC + k0 + c * 8;
            cp16(bs + d, g_Bhi + go);
            cp16(bs + 16384 + d, g_Blo + go);
        }
        cp_commit();
    };

    const int xrow = tid >> 1, xcb = (tid & 1) * 32;
    const float* Xrow = X + (size_t)(m0 + xrow) * DENC + xcb;
    uint32_t soff[4];
#pragma unroll
    for (int j = 0; j < 4; j++)
        soff[j] = swz((uint32_t)(xrow * 128 + (tid & 1) * 64 + 16 * j));

    auto stsA = [&](int st, int k0) {
        float4 xr[8];
#pragma unroll
        for (int j = 0; j < 8; j++) xr[j] = *(const float4*)(Xrow + k0 + 4 * j);
#pragma unroll
        for (int j = 0; j < 4; j++) {
            uint4 h;
            h.x = cvt_h2(xr[2 * j].y,     xr[2 * j].x);
            h.y = cvt_h2(xr[2 * j].w,     xr[2 * j].z);
            h.z = cvt_h2(xr[2 * j + 1].y, xr[2 * j + 1].x);
            h.w = cvt_h2(xr[2 * j + 1].w, xr[2 * j + 1].z);
            *(uint4*)(smb + (AH - base) + st * 16384 + soff[j]) = h;
        }
    };

    const int a_row = warp_m * 32 + ((lane >> 3) & 1) * 8 + (lane & 7);
    const int a_kb  = (lane >> 4) * 16;
    const int b_row = warp_n * 64 + ((lane >> 4) & 1) * 8 + (lane & 7);
    const int b_kb  = ((lane >> 3) & 1) * 16;

    issueB(0, 0);
    issueB(1, KCH);
    stsA(0, 0);

    for (int i = 0; i < NCHUNK; i++) {
        if (i + 1 < NCHUNK) cp_wait<1>(); else cp_wait<0>();
        __syncthreads();

        const uint32_t as = AH + (i & 1) * 16384;
        const uint32_t bs = BQ + (i % 3) * 32768;
#pragma unroll
        for (int k = 0; k < 4; k++) {
            const int kbyte = k * 32;
            uint32_t a[2][4];
#pragma unroll
            for (int mi = 0; mi < 2; mi++) {
                uint32_t ao = swz((uint32_t)((a_row + mi * 16) * 128 + a_kb + kbyte));
                ldsm4(a[mi][0], a[mi][1], a[mi][2], a[mi][3], as + ao);
            }
            uint32_t bh[8][2], bl[8][2];
#pragma unroll
            for (int n2 = 0; n2 < 4; n2++) {
                uint32_t bo = swz((uint32_t)((b_row + n2 * 16) * 128 + b_kb + kbyte));
                ldsm4(bh[2 * n2][0], bh[2 * n2][1], bh[2 * n2 + 1][0], bh[2 * n2 + 1][1],
                      bs + bo);
                ldsm4(bl[2 * n2][0], bl[2 * n2][1], bl[2 * n2 + 1][0], bl[2 * n2 + 1][1],
                      bs + 16384 + bo);
            }
#pragma unroll
            for (int mi = 0; mi < 2; mi++)
#pragma unroll
                for (int ni = 0; ni < 8; ni++) {
                    mma16816(acc[mi][ni], a[mi], bh[ni]);
                    mma16816(acc[mi][ni], a[mi], bl[ni]);
                }
        }

        if (i + 1 < NCHUNK) stsA((i + 1) & 1, (i + 1) * KCH);
        if (i + 2 < NCHUNK) issueB((i + 2) % 3, (i + 2) * KCH);
    }

    const int erow = m0 + warp_m * 32 + (lane >> 2);
    const int ecol = warp_n * 64 + (lane & 3) * 2;
#pragma unroll
    for (int mi = 0; mi < 2; mi++)
#pragma unroll
        for (int ni = 0; ni < 8; ni++) {
            float* p = g_pre + (size_t)(erow + mi * 16) * NCOL + ecol + ni * 8;
            *(float2*)p              = make_float2(acc[mi][ni][0], acc[mi][ni][1]);
            *(float2*)(p + 8 * NCOL) = make_float2(acc[mi][ni][2], acc[mi][ni][3]);
        }
}

// ---------------- Phase 2: single-warp recurrence (smem h-pairs + deep prefetch) ----------------
__device__ __forceinline__ float ex2a(float x) { float y; asm("ex2.approx.f32 %0,%1;" : "=f"(y) : "f"(x)); return y; }
__device__ __forceinline__ float lg2a(float x) { float y; asm("lg2.approx.f32 %0,%1;" : "=f"(y) : "f"(x)); return y; }
__device__ __forceinline__ float tanha(float x) { float y; asm("tanh.approx.f32 %0,%1;" : "=f"(y) : "f"(x)); return y; }
__device__ __forceinline__ float rcpa(float x) { float y; asm("rcp.approx.f32 %0,%1;" : "=f"(y) : "f"(x)); return y; }
__device__ __forceinline__ float sigm_f(float x) { return fmaf(tanha(0.5f * x), 0.5f, 0.5f); }
__device__ __forceinline__ float sp_clip(float x) {
    const float LOG2E = 1.4426950408889634f, LN2 = 0.6931471805599453f;
    float e = ex2a(-fabsf(x) * LOG2E);
    float sp = fmaxf(x, 0.f) + lg2a(1.f + e) * LN2;
    return fminf(fmaxf(sp, 1e-6f), 100.f);
}

// One warp per batch. Lane k<30: hidden unit k; (i,f),(g,o) as f32x2 pairs.
// Lanes 30/31 carry Wa/Wb in the LO half of (i,f) -> a/b logits free.
// h distribution: STS.64 pair + 15 broadcast LDS.128 (no shfl, no pk2 movs).
// Memory: 4-deep LDG.128 prefetch pipeline + precomputed lg2(1-u) in smem.
__global__ __launch_bounds__(32) void seq_kernel(const float* __restrict__ u,
                                                 const float* __restrict__ Wih,
                                                 const float* __restrict__ Whh,
                                                 const float* __restrict__ bih,
                                                 const float* __restrict__ bhh,
                                                 const float* __restrict__ Wa,
                                                 const float* __restrict__ ba,
                                                 const float* __restrict__ Wb,
                                                 const float* __restrict__ bb,
                                                 float* __restrict__ out,
                                                 int b_off) {
    __shared__ __align__(16) unsigned long long h2s[2][32];
    __shared__ float lgu_s[T_STEPS];
    const int b = blockIdx.x + b_off;
    const int lane = threadIdx.x;
    const bool ul = lane < HID;

    unsigned long long w_if[HID], w_go[HID];
    unsigned long long bias_if = 0, bias_go = 0, wz_if = 0, wz_go = 0;

    if (ul) {
        const int ri = lane, rf = 30 + lane, rg = 60 + lane, ro = 90 + lane;
        bias_if = pk2(bih[ri] + bhh[ri], bih[rf] + bhh[rf]);
        bias_go = pk2(bih[rg] + bhh[rg], bih[ro] + bhh[ro]);
        wz_if = pk2(Wih[ri * (DENC + 1) + DENC], Wih[rf * (DENC + 1) + DENC]);
        wz_go = pk2(Wih[rg * (DENC + 1) + DENC], Wih[ro * (DENC + 1) + DENC]);
#pragma unroll
        for (int j = 0; j < HID; j++) {
            w_if[j] = pk2(Whh[ri * HID + j], Whh[rf * HID + j]);
            w_go[j] = pk2(Whh[rg * HID + j], Whh[ro * HID + j]);
        }
    } else {
        // lanes 30/31: a/b logit accumulates in the LO half of the (i,f) pair
        const float* wr = (lane == HID) ? (Wa + DENC) : (Wb + DENC);
        bias_if = pk2((lane == HID) ? ba[0] : bb[0], 0.f);
        bias_go = 0ull;
#pragma unroll
        for (int j = 0; j < HID; j++) {
            w_if[j] = pk2(wr[j], 0.f);
            w_go[j] = 0ull;
        }
    }

    const float* urow = u + b * T_STEPS;
    // precompute lg2(1-u) for all steps (one-time, off the recurrence path)
    for (int i = lane; i < T_STEPS; i += 32) {
        float uu = fminf(fmaxf(urow[i], 1e-5f), 1.f - 1e-5f);
        lgu_s[i] = lg2a(1.f - uu);
    }

    float hx = 0.f, c = 0.f;
    h2s[0][lane] = 0ull;
    h2s[1][lane] = 0ull;
    __syncwarp();

    const float* prow = g_pre + (size_t)b * T_STEPS * NCOL;
    const int col4 = ul ? (4 * lane) : NG;    // lanes 30/31 read (xa,xb,·,·)

    // 4-deep prefetch pipeline (4 outstanding LDG.128 per lane)
    float4 pbuf[4];
#pragma unroll
    for (int q = 0; q < 4; q++)
        pbuf[q] = *(const float4*)(prow + (size_t)q * NCOL + col4);

#pragma unroll 4
    for (int t = 0; t < T_STEPS; t++) {
        float4 p4 = pbuf[t & 3];
        if (t + 4 < T_STEPS)
            pbuf[t & 3] = *(const float4*)(prow + (size_t)(t + 4) * NCOL + col4);
        float lgu = lgu_s[t];

        // lane31's lo-half x-part is xb (p4.y); all others use p4.x
        float xlo = (lane == 31) ? p4.y : p4.x;

        // packed dot over smem h-pairs: 15 broadcast LDS.128, split chains
        unsigned long long aif0 = add2(bias_if, pk2(xlo, p4.y)), aif1 = 0ull;
        unsigned long long ago0 = add2(bias_go, pk2(p4.z, p4.w)), ago1 = 0ull;
        const ulonglong2* hp = (const ulonglong2*)h2s[t & 1];
#pragma unroll
        for (int j = 0; j < HID / 2; j++) {
            ulonglong2 q = hp[j];
            aif0 = ffma2(q.x, w_if[2 * j],     aif0);
            aif1 = ffma2(q.y, w_if[2 * j + 1], aif1);
            ago0 = ffma2(q.x, w_go[2 * j],     ago0);
            ago1 = ffma2(q.y, w_go[2 * j + 1], ago1);
        }
        unsigned long long aif = add2(aif0, aif1);
        unsigned long long ago = add2(ago0, ago1);
        float ai, af, ag, ao;
        upk2(aif, ai, af);
        upk2(ago, ag, ao);

        // HardKuma z (a/b logits are lanes 30/31's ai)
        float inv_ab = rcpa(sp_clip(ai));
        float inva = __shfl_sync(0xffffffffu, inv_ab, 30);
        float invb = __shfl_sync(0xffffffffu, inv_ab, 31);
        float p = ex2a(lgu * invb);
        float s = ex2a(lg2a(1.f - p) * inva);
        float zt = fminf(fmaxf(fmaf(s, 1.2f, -0.1f), 0.f), 1.f);
        if (lane == 0) out[b * T_STEPS + t] = zt;

        // LSTM update (in-register)
        unsigned long long z2 = pk2(zt, zt);
        aif = ffma2(z2, wz_if, aif);
        ago = ffma2(z2, wz_go, ago);
        float gi, gf, gg, go_;
        upk2(aif, gi, gf);
        upk2(ago, gg, go_);
        c = sigm_f(gf) * c + sigm_f(gi) * tanha(gg);
        hx = sigm_f(go_) * tanha(c);

        // publish h pair for next step into the other buffer
        h2s[(t + 1) & 1][lane] = pk2(hx, hx);
        __syncwarp();
    }
}

// ---------------- launch: forked-stream pipeline ----------------
extern "C" void kernel_launch(void* const* d_in, const int* in_sizes, int n_in,
                              void* d_out, int out_size) {
    const float* x   = (const float*)d_in[0];
    const float* u   = (const float*)d_in[1];
    const float* Wih = (const float*)d_in[2];
    const float* Whh = (const float*)d_in[3];
    const float* bih = (const float*)d_in[4];
    const float* bhh = (const float*)d_in[5];
    const float* Wa  = (const float*)d_in[6];
    const float* ba  = (const float*)d_in[7];
    const float* Wb  = (const float*)d_in[8];
    const float* bb  = (const float*)d_in[9];
    float* out = (float*)d_out;

    static bool inited = false;
    static cudaStream_t s1, s2;
    static cudaEvent_t e1, e2, f1, f2;
    if (!inited) {
        cudaStreamCreateWithFlags(&s1, cudaStreamNonBlocking);
        cudaStreamCreateWithFlags(&s2, cudaStreamNonBlocking);
        cudaEventCreateWithFlags(&e1, cudaEventDisableTiming);
        cudaEventCreateWithFlags(&e2, cudaEventDisableTiming);
        cudaEventCreateWithFlags(&f1, cudaEventDisableTiming);
        cudaEventCreateWithFlags(&f2, cudaEventDisableTiming);
        cudaFuncSetAttribute(gemm_kernel, cudaFuncAttributeMaxDynamicSharedMemorySize,
                             SMEM_DYN);
        inited = true;
    }

    // stream 0: pack -> gemm chunk 1 -> gemm chunk 2
    pack_kernel<<<(NCOL * DENC + 255) / 256, 256>>>(Wih, Wa, Wb);
    gemm_kernel<<<128, 256, SMEM_DYN>>>(x, 0);
    cudaEventRecord(e1, 0);
    gemm_kernel<<<128, 256, SMEM_DYN>>>(x, 128);
    cudaEventRecord(e2, 0);

    // side stream 1: seq for batches 0..31 (overlaps gemm chunk 2)
    cudaStreamWaitEvent(s1, e1, 0);
    seq_kernel<<<32, 32, 0, s1>>>(u, Wih, Whh, bih, bhh, Wa, ba, Wb, bb, out, 0);
    cudaEventRecord(f1, s1);

    // side stream 2: seq for batches 32..63
    cudaStreamWaitEvent(s2, e2, 0);
    seq_kernel<<<32, 32, 0, s2>>>(u, Wih, Whh, bih, bhh, Wa, ba, Wb, bb, out, 32);
    cudaEventRecord(f2, s2);

    // join back into the captured origin stream
    cudaStreamWaitEvent(0, f1, 0);
    cudaStreamWaitEvent(0, f2, 0);
}

// round 15
// speedup vs baseline: 1.3847x; 1.0512x over previous
#include <cuda_runtime.h>
#include <cuda_fp16.h>
#include <cstdint>
#include <math.h>

#define T_STEPS 512
#define BATCH   64
#define DENC    1536
#define HID     30
#define NG      120
#define NCOL    128
#define MROWS   (BATCH * T_STEPS)
#define KCH     64
#define NCHUNK  (DENC / KCH)      // 24

// ---------------- device scratch ----------------
// g_pre packed layout: col 4k+g = gate g (i,f,g,o) of unit k; col 120=xa, 121=xb
__device__ float   g_pre[(size_t)MROWS * NCOL];
__device__ __half  g_Bhi[NCOL * DENC];
__device__ __half  g_Blo[NCOL * DENC];

// ---------------- helpers ----------------
__device__ __forceinline__ uint32_t smem_u32(const void* p) {
    uint32_t a;
    asm("{ .reg .u64 t; cvta.to.shared.u64 t, %1; cvt.u32.u64 %0, t; }" : "=r"(a) : "l"(p));
    return a;
}
__device__ __forceinline__ uint32_t swz(uint32_t off) { return off ^ ((off >> 3) & 0x70); }

__device__ __forceinline__ void cp16(uint32_t dst, const void* src) {
    asm volatile("cp.async.cg.shared.global [%0], [%1], 16;" :: "r"(dst), "l"(src));
}
__device__ __forceinline__ void cp_commit() { asm volatile("cp.async.commit_group;"); }
template <int N> __device__ __forceinline__ void cp_wait() {
    asm volatile("cp.async.wait_group %0;" :: "n"(N));
}

__device__ __forceinline__ void ldsm4(uint32_t& r0, uint32_t& r1, uint32_t& r2, uint32_t& r3,
                                      uint32_t addr) {
    asm volatile("ldmatrix.sync.aligned.m8n8.x4.shared.b16 {%0,%1,%2,%3}, [%4];"
                 : "=r"(r0), "=r"(r1), "=r"(r2), "=r"(r3) : "r"(addr));
}
__device__ __forceinline__ void mma16816(float* c, const uint32_t* a, const uint32_t* b) {
    asm volatile(
        "mma.sync.aligned.m16n8k16.row.col.f32.f16.f16.f32 "
        "{%0,%1,%2,%3}, {%4,%5,%6,%7}, {%8,%9}, {%0,%1,%2,%3};"
        : "+f"(c[0]), "+f"(c[1]), "+f"(c[2]), "+f"(c[3])
        : "r"(a[0]), "r"(a[1]), "r"(a[2]), "r"(a[3]), "r"(b[0]), "r"(b[1]));
}
__device__ __forceinline__ uint32_t cvt_h2(float hi, float lo) {
    uint32_t r;
    asm("cvt.rn.f16x2.f32 %0, %1, %2;" : "=r"(r) : "f"(hi), "f"(lo));
    return r;
}

// f32x2 packed helpers
__device__ __forceinline__ unsigned long long pk2(float lo, float hi) {
    unsigned long long r;
    asm("mov.b64 %0, {%1,%2};" : "=l"(r) : "f"(lo), "f"(hi));
    return r;
}
__device__ __forceinline__ void upk2(unsigned long long v, float& lo, float& hi) {
    asm("mov.b64 {%0,%1}, %2;" : "=f"(lo), "=f"(hi) : "l"(v));
}
__device__ __forceinline__ unsigned long long ffma2(unsigned long long a,
                                                    unsigned long long b,
                                                    unsigned long long c) {
    unsigned long long d;
    asm("fma.rn.f32x2 %0, %1, %2, %3;" : "=l"(d) : "l"(a), "l"(b), "l"(c));
    return d;
}
__device__ __forceinline__ unsigned long long add2(unsigned long long a,
                                                   unsigned long long b) {
    unsigned long long d;
    asm("add.rn.f32x2 %0, %1, %2;" : "=l"(d) : "l"(a), "l"(b));
    return d;
}

// ---------------- Phase 0: pack W -> fp16 hi/lo, PERMUTED rows ----------------
// packed row p<120 -> orig gate row (p&3)*30 + (p>>2); p==120 -> Wa; p==121 -> Wb
__global__ void pack_kernel(const float* __restrict__ Wih, const float* __restrict__ Wa,
                            const float* __restrict__ Wb) {
    int idx = blockIdx.x * blockDim.x + threadIdx.x;
    if (idx >= NCOL * DENC) return;
    int n = idx / DENC, k = idx % DENC;
    float v = 0.f;
    if (n < NG) {
        int r = (n & 3) * 30 + (n >> 2);
        v = Wih[r * (DENC + 1) + k];
    } else if (n == NG)     v = Wa[k];
    else if (n == NG + 1)   v = Wb[k];
    __half hi = __float2half_rn(v);
    float r = v - __half2float(hi);
    g_Bhi[idx] = hi;
    g_Blo[idx] = __float2half_rn(r);
}

// ---------------- Phase 1: HMMA GEMM (unchanged) ----------------
#define SMEM_DYN (1024 + 128 * 1024)

__global__ __launch_bounds__(256) void gemm_kernel(const float* __restrict__ X,
                                                   int blk_off) {
    extern __shared__ char dsm[];
    const uint32_t raw = smem_u32(dsm);
    const uint32_t base = (raw + 1023) & ~1023u;
    char* smb = dsm + (base - raw);
    const uint32_t AH = base;
    const uint32_t BQ = base + 32768;

    const int tid = threadIdx.x, lane = tid & 31, wid = tid >> 5;
    const int warp_m = wid & 3, warp_n = wid >> 2;
    const int m0 = (blockIdx.x + blk_off) * 128;

    float acc[2][8][4];
#pragma unroll
    for (int mi = 0; mi < 2; mi++)
#pragma unroll
        for (int ni = 0; ni < 8; ni++)
#pragma unroll
            for (int q = 0; q < 4; q++) acc[mi][ni][q] = 0.f;

    auto issueB = [&](int s, int k0) {
        uint32_t bs = BQ + s * 32768;
#pragma unroll
        for (int j = 0; j < 4; j++) {
            int u = tid + j * 256;
            int row = u >> 3, c = u & 7;
            uint32_t d = swz((uint32_t)(row * 128 + c * 16));
            size_t go = (size_t)row * DENC + k0 + c * 8;
            cp16(bs + d, g_Bhi + go);
            cp16(bs + 16384 + d, g_Blo + go);
        }
        cp_commit();
    };

    const int xrow = tid >> 1, xcb = (tid & 1) * 32;
    const float* Xrow = X + (size_t)(m0 + xrow) * DENC + xcb;
    uint32_t soff[4];
#pragma unroll
    for (int j = 0; j < 4; j++)
        soff[j] = swz((uint32_t)(xrow * 128 + (tid & 1) * 64 + 16 * j));

    auto stsA = [&](int st, int k0) {
        float4 xr[8];
#pragma unroll
        for (int j = 0; j < 8; j++) xr[j] = *(const float4*)(Xrow + k0 + 4 * j);
#pragma unroll
        for (int j = 0; j < 4; j++) {
            uint4 h;
            h.x = cvt_h2(xr[2 * j].y,     xr[2 * j].x);
            h.y = cvt_h2(xr[2 * j].w,     xr[2 * j].z);
            h.z = cvt_h2(xr[2 * j + 1].y, xr[2 * j + 1].x);
            h.w = cvt_h2(xr[2 * j + 1].w, xr[2 * j + 1].z);
            *(uint4*)(smb + (AH - base) + st * 16384 + soff[j]) = h;
        }
    };

    const int a_row = warp_m * 32 + ((lane >> 3) & 1) * 8 + (lane & 7);
    const int a_kb  = (lane >> 4) * 16;
    const int b_row = warp_n * 64 + ((lane >> 4) & 1) * 8 + (lane & 7);
    const int b_kb  = ((lane >> 3) & 1) * 16;

    issueB(0, 0);
    issueB(1, KCH);
    stsA(0, 0);

    for (int i = 0; i < NCHUNK; i++) {
        if (i + 1 < NCHUNK) cp_wait<1>(); else cp_wait<0>();
        __syncthreads();

        const uint32_t as = AH + (i & 1) * 16384;
        const uint32_t bs = BQ + (i % 3) * 32768;
#pragma unroll
        for (int k = 0; k < 4; k++) {
            const int kbyte = k * 32;
            uint32_t a[2][4];
#pragma unroll
            for (int mi = 0; mi < 2; mi++) {
                uint32_t ao = swz((uint32_t)((a_row + mi * 16) * 128 + a_kb + kbyte));
                ldsm4(a[mi][0], a[mi][1], a[mi][2], a[mi][3], as + ao);
            }
            uint32_t bh[8][2], bl[8][2];
#pragma unroll
            for (int n2 = 0; n2 < 4; n2++) {
                uint32_t bo = swz((uint32_t)((b_row + n2 * 16) * 128 + b_kb + kbyte));
                ldsm4(bh[2 * n2][0], bh[2 * n2][1], bh[2 * n2 + 1][0], bh[2 * n2 + 1][1],
                      bs + bo);
                ldsm4(bl[2 * n2][0], bl[2 * n2][1], bl[2 * n2 + 1][0], bl[2 * n2 + 1][1],
                      bs + 16384 + bo);
            }
#pragma unroll
            for (int mi = 0; mi < 2; mi++)
#pragma unroll
                for (int ni = 0; ni < 8; ni++) {
                    mma16816(acc[mi][ni], a[mi], bh[ni]);
                    mma16816(acc[mi][ni], a[mi], bl[ni]);
                }
        }

        if (i + 1 < NCHUNK) stsA((i + 1) & 1, (i + 1) * KCH);
        if (i + 2 < NCHUNK) issueB((i + 2) % 3, (i + 2) * KCH);
    }

    const int erow = m0 + warp_m * 32 + (lane >> 2);
    const int ecol = warp_n * 64 + (lane & 3) * 2;
#pragma unroll
    for (int mi = 0; mi < 2; mi++)
#pragma unroll
        for (int ni = 0; ni < 8; ni++) {
            float* p = g_pre + (size_t)(erow + mi * 16) * NCOL + ecol + ni * 8;
            *(float2*)p              = make_float2(acc[mi][ni][0], acc[mi][ni][1]);
            *(float2*)(p + 8 * NCOL) = make_float2(acc[mi][ni][2], acc[mi][ni][3]);
        }
}

// ---------------- Phase 2: 2-warp cooperative recurrence ----------------
__device__ __forceinline__ float ex2a(float x) { float y; asm("ex2.approx.f32 %0,%1;" : "=f"(y) : "f"(x)); return y; }
__device__ __forceinline__ float lg2a(float x) { float y; asm("lg2.approx.f32 %0,%1;" : "=f"(y) : "f"(x)); return y; }
__device__ __forceinline__ float tanha(float x) { float y; asm("tanh.approx.f32 %0,%1;" : "=f"(y) : "f"(x)); return y; }
__device__ __forceinline__ float rcpa(float x) { float y; asm("rcp.approx.f32 %0,%1;" : "=f"(y) : "f"(x)); return y; }
__device__ __forceinline__ float sigm_f(float x) { return fmaf(tanha(0.5f * x), 0.5f, 0.5f); }
__device__ __forceinline__ float sp_clip(float x) {
    const float LOG2E = 1.4426950408889634f, LN2 = 0.6931471805599453f;
    float e = ex2a(-fabsf(x) * LOG2E);
    float sp = fmaxf(x, 0.f) + lg2a(1.f + e) * LN2;
    return fminf(fmaxf(sp, 1e-6f), 100.f);
}
__device__ __forceinline__ void barrier64() {
    asm volatile("bar.sync 0, 64;" ::: "memory");
}

// One CTA (64 threads = 2 warps) per batch.
//  warp0: (i,f) packed dot via shfl (Wa/Wb folded into lanes 30/31 lo half),
//         z MUFU chain, LSTM (hx lives in warp0 regs), publishes h pairs.
//  warp1: (g,o) packed dot reading h pairs from smem, publishes ago.
// Memory: 4-deep LDG.128 prefetch + precomputed lg2(1-u) (proven R12 machinery).
__global__ __launch_bounds__(64) void seq_kernel(const float* __restrict__ u,
                                                 const float* __restrict__ Wih,
                                                 const float* __restrict__ Whh,
                                                 const float* __restrict__ bih,
                                                 const float* __restrict__ bhh,
                                                 const float* __restrict__ Wa,
                                                 const float* __restrict__ ba,
                                                 const float* __restrict__ Wb,
                                                 const float* __restrict__ bb,
                                                 float* __restrict__ out,
                                                 int b_off) {
    __shared__ __align__(16) unsigned long long h2s[32];
    __shared__ __align__(16) unsigned long long ago_s[32];
    __shared__ float lgu_s[T_STEPS];
    const int b = blockIdx.x + b_off;
    const int tid = threadIdx.x, lane = tid & 31, wid = tid >> 5;
    const bool ul = lane < HID;

    const float* urow = u + b * T_STEPS;
    for (int i = tid; i < T_STEPS; i += 64) {
        float uu = fminf(fmaxf(urow[i], 1e-5f), 1.f - 1e-5f);
        lgu_s[i] = lg2a(1.f - uu);
    }
    if (tid < 32) { h2s[tid] = 0ull; ago_s[tid] = 0ull; }

    const float* prow = g_pre + (size_t)b * T_STEPS * NCOL;
    const int col4 = ul ? (4 * lane) : NG;    // lanes 30/31 read (xa,xb,·,·)

    __syncthreads();

    if (wid == 0) {
        // ---------- warp 0: (i,f) + a/b + z + LSTM ----------
        unsigned long long w_if[HID];
        unsigned long long bias_if = 0, wzA = 0, wzB = 0;
        if (ul) {
            const int ri = lane, rf = 30 + lane, rg = 60 + lane, ro = 90 + lane;
            bias_if = pk2(bih[ri] + bhh[ri], bih[rf] + bhh[rf]);
            wzA = pk2(Wih[ri * (DENC + 1) + DENC], Wih[rf * (DENC + 1) + DENC]);
            wzB = pk2(Wih[rg * (DENC + 1) + DENC], Wih[ro * (DENC + 1) + DENC]);
#pragma unroll
            for (int j = 0; j < HID; j++)
                w_if[j] = pk2(Whh[lane * HID + j], Whh[(30 + lane) * HID + j]);
        } else {
            const float* wr = (lane == HID) ? (Wa + DENC) : (Wb + DENC);
            bias_if = pk2((lane == HID) ? ba[0] : bb[0], 0.f);
#pragma unroll
            for (int j = 0; j < HID; j++) w_if[j] = pk2(wr[j], 0.f);
        }

        float hx = 0.f, c = 0.f;
        float4 pbuf[4];
#pragma unroll
        for (int q = 0; q < 4; q++)
            pbuf[q] = *(const float4*)(prow + (size_t)q * NCOL + col4);

#pragma unroll 4
        for (int t = 0; t < T_STEPS; t++) {
            float4 p4 = pbuf[t & 3];
            if (t + 4 < T_STEPS)
                pbuf[t & 3] = *(const float4*)(prow + (size_t)(t + 4) * NCOL + col4);
            float lgu = lgu_s[t];

            // lane31's lo-half x-part is xb (p4.y); all others use p4.x
            float xlo = (lane == 31) ? p4.y : p4.x;
            unsigned long long aif = add2(bias_if, pk2(xlo, p4.y));
#pragma unroll
            for (int j = 0; j < HID; j++) {
                float h = __shfl_sync(0xffffffffu, hx, j);
                aif = ffma2(pk2(h, h), w_if[j], aif);
            }
            float ai, af;
            upk2(aif, ai, af);

            // HardKuma z (a/b logits are lanes 30/31's ai)
            float inv_ab = rcpa(sp_clip(ai));
            float inva = __shfl_sync(0xffffffffu, inv_ab, 30);
            float invb = __shfl_sync(0xffffffffu, inv_ab, 31);
            float p = ex2a(lgu * invb);
            float s = ex2a(lg2a(1.f - p) * inva);
            float zt = fminf(fmaxf(fmaf(s, 1.2f, -0.1f), 0.f), 1.f);
            if (lane == 0) out[b * T_STEPS + t] = zt;

            barrier64();                    // (1) ago published by warp1

            unsigned long long z2 = pk2(zt, zt);
            aif = ffma2(z2, wzA, aif);
            unsigned long long ago = ago_s[lane];
            ago = ffma2(z2, wzB, ago);
            float gi, gf, gg, go_;
            upk2(aif, gi, gf);
            upk2(ago, gg, go_);
            c = sigm_f(gf) * c + sigm_f(gi) * tanha(gg);
            hx = sigm_f(go_) * tanha(c);
            h2s[lane] = pk2(hx, hx);

            barrier64();                    // (2) h published for warp1
        }
    } else {
        // ---------- warp 1: (g,o) dot ----------
        unsigned long long w_go[HID];
        unsigned long long bias_go = 0;
        if (ul) {
            const int rg = 60 + lane, ro = 90 + lane;
            bias_go = pk2(bih[rg] + bhh[rg], bih[ro] + bhh[ro]);
#pragma unroll
            for (int j = 0; j < HID; j++)
                w_go[j] = pk2(Whh[rg * HID + j], Whh[ro * HID + j]);
        } else {
#pragma unroll
            for (int j = 0; j < HID; j++) w_go[j] = 0ull;
        }

        float4 pbuf[4];
#pragma unroll
        for (int q = 0; q < 4; q++)
            pbuf[q] = *(const float4*)(prow + (size_t)q * NCOL + col4);

#pragma unroll 4
        for (int t = 0; t < T_STEPS; t++) {
            float4 p4 = pbuf[t & 3];
            if (t + 4 < T_STEPS)
                pbuf[t & 3] = *(const float4*)(prow + (size_t)(t + 4) * NCOL + col4);

            unsigned long long acc0 = add2(bias_go, pk2(p4.z, p4.w)), acc1 = 0ull;
            const ulonglong2* hp = (const ulonglong2*)h2s;
#pragma unroll
            for (int j = 0; j < HID / 2; j++) {
                ulonglong2 q = hp[j];
                acc0 = ffma2(q.x, w_go[2 * j],     acc0);
                acc1 = ffma2(q.y, w_go[2 * j + 1], acc1);
            }
            ago_s[lane] = add2(acc0, acc1);

            barrier64();                    // (1) ago visible to warp0
            barrier64();                    // (2) wait for h(t)
        }
    }
}

// ---------------- launch: forked-stream pipeline ----------------
extern "C" void kernel_launch(void* const* d_in, const int* in_sizes, int n_in,
                              void* d_out, int out_size) {
    const float* x   = (const float*)d_in[0];
    const float* u   = (const float*)d_in[1];
    const float* Wih = (const float*)d_in[2];
    const float* Whh = (const float*)d_in[3];
    const float* bih = (const float*)d_in[4];
    const float* bhh = (const float*)d_in[5];
    const float* Wa  = (const float*)d_in[6];
    const float* ba  = (const float*)d_in[7];
    const float* Wb  = (const float*)d_in[8];
    const float* bb  = (const float*)d_in[9];
    float* out = (float*)d_out;

    static bool inited = false;
    static cudaStream_t s1, s2;
    static cudaEvent_t e1, e2, f1, f2;
    if (!inited) {
        cudaStreamCreateWithFlags(&s1, cudaStreamNonBlocking);
        cudaStreamCreateWithFlags(&s2, cudaStreamNonBlocking);
        cudaEventCreateWithFlags(&e1, cudaEventDisableTiming);
        cudaEventCreateWithFlags(&e2, cudaEventDisableTiming);
        cudaEventCreateWithFlags(&f1, cudaEventDisableTiming);
        cudaEventCreateWithFlags(&f2, cudaEventDisableTiming);
        cudaFuncSetAttribute(gemm_kernel, cudaFuncAttributeMaxDynamicSharedMemorySize,
                             SMEM_DYN);
        inited = true;
    }

    // stream 0: pack -> gemm chunk 1 -> gemm chunk 2
    pack_kernel<<<(NCOL * DENC + 255) / 256, 256>>>(Wih, Wa, Wb);
    gemm_kernel<<<128, 256, SMEM_DYN>>>(x, 0);
    cudaEventRecord(e1, 0);
    gemm_kernel<<<128, 256, SMEM_DYN>>>(x, 128);
    cudaEventRecord(e2, 0);

    // side stream 1: seq for batches 0..31 (overlaps gemm chunk 2)
    cudaStreamWaitEvent(s1, e1, 0);
    seq_kernel<<<32, 64, 0, s1>>>(u, Wih, Whh, bih, bhh, Wa, ba, Wb, bb, out, 0);
    cudaEventRecord(f1, s1);

    // side stream 2: seq for batches 32..63
    cudaStreamWaitEvent(s2, e2, 0);
    seq_kernel<<<32, 64, 0, s2>>>(u, Wih, Whh, bih, bhh, Wa, ba, Wb, bb, out, 32);
    cudaEventRecord(f2, s2);

    // join back into the captured origin stream
    cudaStreamWaitEvent(0, f1, 0);
    cudaStreamWaitEvent(0, f2, 0);
}

// round 16
// speedup vs baseline: 1.4941x; 1.0790x over previous
#include <cuda_runtime.h>
#include <cuda_fp16.h>
#include <cstdint>
#include <math.h>

#define T_STEPS 512
#define BATCH   64
#define DENC    1536
#define HID     30
#define NG      120
#define NCOL    128
#define MROWS   (BATCH * T_STEPS)
#define KCH     64
#define NCHUNK  (DENC / KCH)      // 24

// ---------------- device scratch ----------------
// g_pre packed layout: col 4k+g = gate g (i,f,g,o) of unit k; col 120=xa, 121=xb
__device__ float   g_pre[(size_t)MROWS * NCOL];
__device__ __half  g_Bhi[NCOL * DENC];

// ---------------- helpers ----------------
__device__ __forceinline__ uint32_t smem_u32(const void* p) {
    uint32_t a;
    asm("{ .reg .u64 t; cvta.to.shared.u64 t, %1; cvt.u32.u64 %0, t; }" : "=r"(a) : "l"(p));
    return a;
}
__device__ __forceinline__ uint32_t swz(uint32_t off) { return off ^ ((off >> 3) & 0x70); }

__device__ __forceinline__ void cp16(uint32_t dst, const void* src) {
    asm volatile("cp.async.cg.shared.global [%0], [%1], 16;" :: "r"(dst), "l"(src));
}
__device__ __forceinline__ void cp_commit() { asm volatile("cp.async.commit_group;"); }
template <int N> __device__ __forceinline__ void cp_wait() {
    asm volatile("cp.async.wait_group %0;" :: "n"(N));
}

__device__ __forceinline__ void ldsm4(uint32_t& r0, uint32_t& r1, uint32_t& r2, uint32_t& r3,
                                      uint32_t addr) {
    asm volatile("ldmatrix.sync.aligned.m8n8.x4.shared.b16 {%0,%1,%2,%3}, [%4];"
                 : "=r"(r0), "=r"(r1), "=r"(r2), "=r"(r3) : "r"(addr));
}
__device__ __forceinline__ void mma16816(float* c, const uint32_t* a, const uint32_t* b) {
    asm volatile(
        "mma.sync.aligned.m16n8k16.row.col.f32.f16.f16.f32 "
        "{%0,%1,%2,%3}, {%4,%5,%6,%7}, {%8,%9}, {%0,%1,%2,%3};"
        : "+f"(c[0]), "+f"(c[1]), "+f"(c[2]), "+f"(c[3])
        : "r"(a[0]), "r"(a[1]), "r"(a[2]), "r"(a[3]), "r"(b[0]), "r"(b[1]));
}
__device__ __forceinline__ uint32_t cvt_h2(float hi, float lo) {
    uint32_t r;
    asm("cvt.rn.f16x2.f32 %0, %1, %2;" : "=r"(r) : "f"(hi), "f"(lo));
    return r;
}

// f32x2 packed helpers
__device__ __forceinline__ unsigned long long pk2(float lo, float hi) {
    unsigned long long r;
    asm("mov.b64 %0, {%1,%2};" : "=l"(r) : "f"(lo), "f"(hi));
    return r;
}
__device__ __forceinline__ void upk2(unsigned long long v, float& lo, float& hi) {
    asm("mov.b64 {%0,%1}, %2;" : "=f"(lo), "=f"(hi) : "l"(v));
}
__device__ __forceinline__ unsigned long long ffma2(unsigned long long a,
                                                    unsigned long long b,
                                                    unsigned long long c) {
    unsigned long long d;
    asm("fma.rn.f32x2 %0, %1, %2, %3;" : "=l"(d) : "l"(a), "l"(b), "l"(c));
    return d;
}
__device__ __forceinline__ unsigned long long add2(unsigned long long a,
                                                   unsigned long long b) {
    unsigned long long d;
    asm("add.rn.f32x2 %0, %1, %2;" : "=l"(d) : "l"(a), "l"(b));
    return d;
}

// ---------------- Phase 0: pack W -> fp16 hi, PERMUTED rows ----------------
// packed row p<120 -> orig gate row (p&3)*30 + (p>>2); p==120 -> Wa; p==121 -> Wb
__global__ void pack_kernel(const float* __restrict__ Wih, const float* __restrict__ Wa,
                            const float* __restrict__ Wb) {
    int idx = blockIdx.x * blockDim.x + threadIdx.x;
    if (idx >= NCOL * DENC) return;
    int n = idx / DENC, k = idx % DENC;
    float v = 0.f;
    if (n < NG) {
        int r = (n & 3) * 30 + (n >> 2);
        v = Wih[r * (DENC + 1) + k];
    } else if (n == NG)     v = Wa[k];
    else if (n == NG + 1)   v = Wb[k];
    g_Bhi[idx] = __float2half_rn(v);
}

// ---------------- Phase 1: HMMA GEMM (hi x hi only) ----------------
// smem: A 2 stages x 16K | B 3 stages x 16K
#define SMEM_DYN (1024 + 80 * 1024)

__global__ __launch_bounds__(256) void gemm_kernel(const float* __restrict__ X,
                                                   int blk_off) {
    extern __shared__ char dsm[];
    const uint32_t raw = smem_u32(dsm);
    const uint32_t base = (raw + 1023) & ~1023u;
    char* smb = dsm + (base - raw);
    const uint32_t AH = base;            // + st*16384
    const uint32_t BQ = base + 32768;    // + s*16384

    const int tid = threadIdx.x, lane = tid & 31, wid = tid >> 5;
    const int warp_m = wid & 3, warp_n = wid >> 2;
    const int m0 = (blockIdx.x + blk_off) * 128;

    float acc[2][8][4];
#pragma unroll
    for (int mi = 0; mi < 2; mi++)
#pragma unroll
        for (int ni = 0; ni < 8; ni++)
#pragma unroll
            for (int q = 0; q < 4; q++) acc[mi][ni][q] = 0.f;

    auto issueB = [&](int s, int k0) {
        uint32_t bs = BQ + s * 16384;
#pragma unroll
        for (int j = 0; j < 4; j++) {
            int u = tid + j * 256;
            int row = u >> 3, c = u & 7;
            uint32_t d = swz((uint32_t)(row * 128 + c * 16));
            size_t go = (size_t)row * DENC + k0 + c * 8;
            cp16(bs + d, g_Bhi + go);
        }
        cp_commit();
    };

    const int xrow = tid >> 1, xcb = (tid & 1) * 32;
    const float* Xrow = X + (size_t)(m0 + xrow) * DENC + xcb;
    uint32_t soff[4];
#pragma unroll
    for (int j = 0; j < 4; j++)
        soff[j] = swz((uint32_t)(xrow * 128 + (tid & 1) * 64 + 16 * j));

    auto stsA = [&](int st, int k0) {
        float4 xr[8];
#pragma unroll
        for (int j = 0; j < 8; j++) xr[j] = *(const float4*)(Xrow + k0 + 4 * j);
#pragma unroll
        for (int j = 0; j < 4; j++) {
            uint4 h;
            h.x = cvt_h2(xr[2 * j].y,     xr[2 * j].x);
            h.y = cvt_h2(xr[2 * j].w,     xr[2 * j].z);
            h.z = cvt_h2(xr[2 * j + 1].y, xr[2 * j + 1].x);
            h.w = cvt_h2(xr[2 * j + 1].w, xr[2 * j + 1].z);
            *(uint4*)(smb + (AH - base) + st * 16384 + soff[j]) = h;
        }
    };

    const int a_row = warp_m * 32 + ((lane >> 3) & 1) * 8 + (lane & 7);
    const int a_kb  = (lane >> 4) * 16;
    const int b_row = warp_n * 64 + ((lane >> 4) & 1) * 8 + (lane & 7);
    const int b_kb  = ((lane >> 3) & 1) * 16;

    issueB(0, 0);
    issueB(1, KCH);
    stsA(0, 0);

    for (int i = 0; i < NCHUNK; i++) {
        if (i + 1 < NCHUNK) cp_wait<1>(); else cp_wait<0>();
        __syncthreads();

        const uint32_t as = AH + (i & 1) * 16384;
        const uint32_t bs = BQ + (i % 3) * 16384;
#pragma unroll
        for (int k = 0; k < 4; k++) {
            const int kbyte = k * 32;
            uint32_t a[2][4];
#pragma unroll
            for (int mi = 0; mi < 2; mi++) {
                uint32_t ao = swz((uint32_t)((a_row + mi * 16) * 128 + a_kb + kbyte));
                ldsm4(a[mi][0], a[mi][1], a[mi][2], a[mi][3], as + ao);
            }
            uint32_t bh[8][2];
#pragma unroll
            for (int n2 = 0; n2 < 4; n2++) {
                uint32_t bo = swz((uint32_t)((b_row + n2 * 16) * 128 + b_kb + kbyte));
                ldsm4(bh[2 * n2][0], bh[2 * n2][1], bh[2 * n2 + 1][0], bh[2 * n2 + 1][1],
                      bs + bo);
            }
#pragma unroll
            for (int mi = 0; mi < 2; mi++)
#pragma unroll
                for (int ni = 0; ni < 8; ni++)
                    mma16816(acc[mi][ni], a[mi], bh[ni]);
        }

        if (i + 1 < NCHUNK) stsA((i + 1) & 1, (i + 1) * KCH);
        if (i + 2 < NCHUNK) issueB((i + 2) % 3, (i + 2) * KCH);
    }

    const int erow = m0 + warp_m * 32 + (lane >> 2);
    const int ecol = warp_n * 64 + (lane & 3) * 2;
#pragma unroll
    for (int mi = 0; mi < 2; mi++)
#pragma unroll
        for (int ni = 0; ni < 8; ni++) {
            float* p = g_pre + (size_t)(erow + mi * 16) * NCOL + ecol + ni * 8;
            *(float2*)p              = make_float2(acc[mi][ni][0], acc[mi][ni][1]);
            *(float2*)(p + 8 * NCOL) = make_float2(acc[mi][ni][2], acc[mi][ni][3]);
        }
}

// ---------------- Phase 2: 2-warp cooperative recurrence (R15) ----------------
__device__ __forceinline__ float ex2a(float x) { float y; asm("ex2.approx.f32 %0,%1;" : "=f"(y) : "f"(x)); return y; }
__device__ __forceinline__ float lg2a(float x) { float y; asm("lg2.approx.f32 %0,%1;" : "=f"(y) : "f"(x)); return y; }
__device__ __forceinline__ float tanha(float x) { float y; asm("tanh.approx.f32 %0,%1;" : "=f"(y) : "f"(x)); return y; }
__device__ __forceinline__ float rcpa(float x) { float y; asm("rcp.approx.f32 %0,%1;" : "=f"(y) : "f"(x)); return y; }
__device__ __forceinline__ float sigm_f(float x) { return fmaf(tanha(0.5f * x), 0.5f, 0.5f); }
__device__ __forceinline__ float sp_clip(float x) {
    const float LOG2E = 1.4426950408889634f, LN2 = 0.6931471805599453f;
    float e = ex2a(-fabsf(x) * LOG2E);
    float sp = fmaxf(x, 0.f) + lg2a(1.f + e) * LN2;
    return fminf(fmaxf(sp, 1e-6f), 100.f);
}
__device__ __forceinline__ void barrier64() {
    asm volatile("bar.sync 0, 64;" ::: "memory");
}

__global__ __launch_bounds__(64) void seq_kernel(const float* __restrict__ u,
                                                 const float* __restrict__ Wih,
                                                 const float* __restrict__ Whh,
                                                 const float* __restrict__ bih,
                                                 const float* __restrict__ bhh,
                                                 const float* __restrict__ Wa,
                                                 const float* __restrict__ ba,
                                                 const float* __restrict__ Wb,
                                                 const float* __restrict__ bb,
                                                 float* __restrict__ out,
                                                 int b_off) {
    __shared__ __align__(16) unsigned long long h2s[32];
    __shared__ __align__(16) unsigned long long ago_s[32];
    __shared__ float lgu_s[T_STEPS];
    const int b = blockIdx.x + b_off;
    const int tid = threadIdx.x, lane = tid & 31, wid = tid >> 5;
    const bool ul = lane < HID;

    const float* urow = u + b * T_STEPS;
    for (int i = tid; i < T_STEPS; i += 64) {
        float uu = fminf(fmaxf(urow[i], 1e-5f), 1.f - 1e-5f);
        lgu_s[i] = lg2a(1.f - uu);
    }
    if (tid < 32) { h2s[tid] = 0ull; ago_s[tid] = 0ull; }

    const float* prow = g_pre + (size_t)b * T_STEPS * NCOL;
    const int col4 = ul ? (4 * lane) : NG;    // lanes 30/31 read (xa,xb,·,·)

    __syncthreads();

    if (wid == 0) {
        // ---------- warp 0: (i,f) + a/b + z + LSTM ----------
        unsigned long long w_if[HID];
        unsigned long long bias_if = 0, wzA = 0, wzB = 0;
        if (ul) {
            const int ri = lane, rf = 30 + lane, rg = 60 + lane, ro = 90 + lane;
            bias_if = pk2(bih[ri] + bhh[ri], bih[rf] + bhh[rf]);
            wzA = pk2(Wih[ri * (DENC + 1) + DENC], Wih[rf * (DENC + 1) + DENC]);
            wzB = pk2(Wih[rg * (DENC + 1) + DENC], Wih[ro * (DENC + 1) + DENC]);
#pragma unroll
            for (int j = 0; j < HID; j++)
                w_if[j] = pk2(Whh[lane * HID + j], Whh[(30 + lane) * HID + j]);
        } else {
            const float* wr = (lane == HID) ? (Wa + DENC) : (Wb + DENC);
            bias_if = pk2((lane == HID) ? ba[0] : bb[0], 0.f);
#pragma unroll
            for (int j = 0; j < HID; j++) w_if[j] = pk2(wr[j], 0.f);
        }

        float hx = 0.f, c = 0.f;
        float4 pbuf[4];
#pragma unroll
        for (int q = 0; q < 4; q++)
            pbuf[q] = *(const float4*)(prow + (size_t)q * NCOL + col4);

#pragma unroll 4
        for (int t = 0; t < T_STEPS; t++) {
            float4 p4 = pbuf[t & 3];
            if (t + 4 < T_STEPS)
                pbuf[t & 3] = *(const float4*)(prow + (size_t)(t + 4) * NCOL + col4);
            float lgu = lgu_s[t];

            float xlo = (lane == 31) ? p4.y : p4.x;
            unsigned long long aif = add2(bias_if, pk2(xlo, p4.y));
#pragma unroll
            for (int j = 0; j < HID; j++) {
                float h = __shfl_sync(0xffffffffu, hx, j);
                aif = ffma2(pk2(h, h), w_if[j], aif);
            }
            float ai, af;
            upk2(aif, ai, af);

            float inv_ab = rcpa(sp_clip(ai));
            float inva = __shfl_sync(0xffffffffu, inv_ab, 30);
            float invb = __shfl_sync(0xffffffffu, inv_ab, 31);
            float p = ex2a(lgu * invb);
            float s = ex2a(lg2a(1.f - p) * inva);
            float zt = fminf(fmaxf(fmaf(s, 1.2f, -0.1f), 0.f), 1.f);
            if (lane == 0) out[b * T_STEPS + t] = zt;

            barrier64();                    // (1) ago published by warp1

            unsigned long long z2 = pk2(zt, zt);
            aif = ffma2(z2, wzA, aif);
            unsigned long long ago = ago_s[lane];
            ago = ffma2(z2, wzB, ago);
            float gi, gf, gg, go_;
            upk2(aif, gi, gf);
            upk2(ago, gg, go_);
            c = sigm_f(gf) * c + sigm_f(gi) * tanha(gg);
            hx = sigm_f(go_) * tanha(c);
            h2s[lane] = pk2(hx, hx);

            barrier64();                    // (2) h published for warp1
        }
    } else {
        // ---------- warp 1: (g,o) dot ----------
        unsigned long long w_go[HID];
        unsigned long long bias_go = 0;
        if (ul) {
            const int rg = 60 + lane, ro = 90 + lane;
            bias_go = pk2(bih[rg] + bhh[rg], bih[ro] + bhh[ro]);
#pragma unroll
            for (int j = 0; j < HID; j++)
                w_go[j] = pk2(Whh[rg * HID + j], Whh[ro * HID + j]);
        } else {
#pragma unroll
            for (int j = 0; j < HID; j++) w_go[j] = 0ull;
        }

        float4 pbuf[4];
#pragma unroll
        for (int q = 0; q < 4; q++)
            pbuf[q] = *(const float4*)(prow + (size_t)q * NCOL + col4);

#pragma unroll 4
        for (int t = 0; t < T_STEPS; t++) {
            float4 p4 = pbuf[t & 3];
            if (t + 4 < T_STEPS)
                pbuf[t & 3] = *(const float4*)(prow + (size_t)(t + 4) * NCOL + col4);

            unsigned long long acc0 = add2(bias_go, pk2(p4.z, p4.w)), acc1 = 0ull;
            const ulonglong2* hp = (const ulonglong2*)h2s;
#pragma unroll
            for (int j = 0; j < HID / 2; j++) {
                ulonglong2 q = hp[j];
                acc0 = ffma2(q.x, w_go[2 * j],     acc0);
                acc1 = ffma2(q.y, w_go[2 * j + 1], acc1);
            }
            ago_s[lane] = add2(acc0, acc1);

            barrier64();                    // (1) ago visible to warp0
            barrier64();                    // (2) wait for h(t)
        }
    }
}

// ---------------- launch: forked-stream pipeline ----------------
extern "C" void kernel_launch(void* const* d_in, const int* in_sizes, int n_in,
                              void* d_out, int out_size) {
    const float* x   = (const float*)d_in[0];
    const float* u   = (const float*)d_in[1];
    const float* Wih = (const float*)d_in[2];
    const float* Whh = (const float*)d_in[3];
    const float* bih = (const float*)d_in[4];
    const float* bhh = (const float*)d_in[5];
    const float* Wa  = (const float*)d_in[6];
    const float* ba  = (const float*)d_in[7];
    const float* Wb  = (const float*)d_in[8];
    const float* bb  = (const float*)d_in[9];
    float* out = (float*)d_out;

    static bool inited = false;
    static cudaStream_t s1, s2;
    static cudaEvent_t e1, e2, f1, f2;
    if (!inited) {
        cudaStreamCreateWithFlags(&s1, cudaStreamNonBlocking);
        cudaStreamCreateWithFlags(&s2, cudaStreamNonBlocking);
        cudaEventCreateWithFlags(&e1, cudaEventDisableTiming);
        cudaEventCreateWithFlags(&e2, cudaEventDisableTiming);
        cudaEventCreateWithFlags(&f1, cudaEventDisableTiming);
        cudaEventCreateWithFlags(&f2, cudaEventDisableTiming);
        cudaFuncSetAttribute(gemm_kernel, cudaFuncAttributeMaxDynamicSharedMemorySize,
                             SMEM_DYN);
        inited = true;
    }

    // stream 0: pack -> gemm chunk 1 -> gemm chunk 2
    pack_kernel<<<(NCOL * DENC + 255) / 256, 256>>>(Wih, Wa, Wb);
    gemm_kernel<<<128, 256, SMEM_DYN>>>(x, 0);
    cudaEventRecord(e1, 0);
    gemm_kernel<<<128, 256, SMEM_DYN>>>(x, 128);
    cudaEventRecord(e2, 0);

    // side stream 1: seq for batches 0..31 (overlaps gemm chunk 2)
    cudaStreamWaitEvent(s1, e1, 0);
    seq_kernel<<<32, 64, 0, s1>>>(u, Wih, Whh, bih, bhh, Wa, ba, Wb, bb, out, 0);
    cudaEventRecord(f1, s1);

    // side stream 2: seq for batches 32..63
    cudaStreamWaitEvent(s2, e2, 0);
    seq_kernel<<<32, 64, 0, s2>>>(u, Wih, Whh, bih, bhh, Wa, ba, Wb, bb, out, 32);
    cudaEventRecord(f2, s2);

    // join back into the captured origin stream
    cudaStreamWaitEvent(0, f1, 0);
    cudaStreamWaitEvent(0, f2, 0);
}